// round 8
// baseline (speedup 1.0000x reference)
#include <cuda_runtime.h>
#include <math.h>

#define NEGV (-1e30f)

// B=8, S=512, L=32, M=64
#define B_ 8
#define S_ 512
#define L_ 32
#define M_ 64
#define SP_ (S_ + 2)          // padded frames: prefetch never needs a frame bounds check
#define LOG2E_ 1.4426950408889634f
#define LN2_   0.6931471805599453f
#define LH_ 16                // labels per CTA (cluster of 2)

// scratch[b][e][cur][jm1] = segment_score[b][e-jm1][e][cur] * LOG2E  (log2 domain)
// +64 pad: lane31's unconditional psb prefetch may read one element past the last row.
__device__ float g_scratch[B_ * SP_ * L_ * M_ + 64];

__device__ __forceinline__ float ex2f(float x) {
    float y; asm("ex2.approx.ftz.f32 %0, %1;" : "=f"(y) : "f"(x)); return y;
}
__device__ __forceinline__ float lg2f(float x) {
    float y; asm("lg2.approx.ftz.f32 %0, %1;" : "=f"(y) : "f"(x)); return y;
}
__device__ __forceinline__ float redux_max_f32(float x) {
    unsigned u = __float_as_uint(x);
    unsigned k = u ^ (((unsigned)((int)u >> 31)) | 0x80000000u);      // monotone key
    unsigned r = __reduce_max_sync(0xffffffffu, k);
    return __uint_as_float(r ^ ((~((unsigned)((int)r >> 31))) | 0x80000000u));
}
__device__ __forceinline__ unsigned smem_u32(const void* p) {
    unsigned a;
    asm("{ .reg .u64 t; cvta.to.shared.u64 t, %1; cvt.u32.u64 %0, t; }" : "=r"(a) : "l"(p));
    return a;
}
__device__ __forceinline__ unsigned mapa_u32(unsigned l, unsigned rank) {
    unsigned r; asm("mapa.shared::cluster.u32 %0, %1, %2;" : "=r"(r) : "r"(l), "r"(rank));
    return r;
}
#define ARRIVE_REMOTE(a) \
    asm volatile("mbarrier.arrive.release.cluster.shared::cluster.b64 _, [%0];" :: "r"(a) : "memory")
#define ST_REMOTE_V2(a, x, y) \
    asm volatile("st.shared::cluster.v2.f32 [%0], {%1, %2};" :: "r"(a), "f"(x), "f"(y) : "memory")
#define WAITP(addr, par) do { unsigned _d;                                                   \
    do { asm volatile("{\n\t.reg .pred P;\n\t"                                               \
        "mbarrier.try_wait.parity.acquire.cluster.shared::cta.b64 P, [%1], %2, 0x989680;\n\t"\
        "selp.b32 %0, 1, 0, P;\n\t}"                                                         \
        : "=r"(_d) : "r"(addr), "r"(par) : "memory"); } while (!_d); } while (0)

// -------- pre-pass: gather band into contiguous [b][e][cur][jm1] layout, log2-scaled --------
__global__ void transpose_kernel(const float* __restrict__ seg) {
    int be = blockIdx.x;
    int b = be >> 9;
    int e = be & (S_ - 1);
    __shared__ float tile[L_][M_ + 1];
    int tid = threadIdx.x;
    for (int idx = tid; idx < M_ * L_; idx += 256) {
        int jm1 = idx >> 5;
        int c   = idx & 31;
        float v = 0.0f;
        int s = e - jm1;
        if (s >= 0) v = seg[(((size_t)b * S_ + s) * S_ + e) * L_ + c] * LOG2E_;
        tile[c][jm1] = v;
    }
    __syncthreads();
    float* out = &g_scratch[((size_t)(b * SP_ + e)) * (L_ * M_)];
    for (int idx = tid; idx < L_ * M_; idx += 256) {
        int c   = idx >> 6;
        int jm1 = idx & 63;
        out[idx] = tile[c][jm1];
    }
}

// -------- sequential recurrence: 2-CTA cluster per batch, 16 warps/CTA, warp = cur label --------
__global__ __launch_bounds__(512, 1) __cluster_dims__(2, 1, 1)
void crf_kernel(const float* __restrict__ trans, float* __restrict__ out) {
    __shared__ float2 s_alpha[2][L_];                 // full 32 labels, peer half pushed via DSMEM
    __shared__ float  s_beta[M_ * (LH_ + 1)];         // per-local-label beta ring
    __shared__ __align__(8) unsigned long long s_mbar[2];

    const int b    = blockIdx.x >> 1;
    unsigned rank; asm("mov.u32 %0, %%cluster_ctarank;" : "=r"(rank));
    const unsigned peer = rank ^ 1u;
    const int tid  = threadIdx.x;
    const int w    = tid >> 5;                        // local warp id 0..15
    const int lane = tid & 31;
    const bool lane0  = (lane == 0);
    const bool lane31 = (lane == 31);
    const int cur  = (int)rank * LH_ + w;             // this warp's label

    const float treg23 = trans[lane * L_ + cur] * LOG2E_ + 23.0f;
    const float diag   = trans[cur * L_ + cur] * LOG2E_;
    const float* seg_base = &g_scratch[((size_t)(b * SP_)) * (L_ * M_)];

    if (tid == 0) {
        asm volatile("mbarrier.init.shared.b64 [%0], %1;" :: "r"(smem_u32(&s_mbar[0])), "r"(LH_) : "memory");
        asm volatile("mbarrier.init.shared.b64 [%0], %1;" :: "r"(smem_u32(&s_mbar[1])), "r"(LH_) : "memory");
    }
    for (int i = tid; i < M_ * (LH_ + 1); i += 512) s_beta[i] = NEGV;
    if (tid < L_) s_alpha[0][tid] = make_float2(seg_base[tid * M_], 1.0f);  // both CTAs load all 32
    __syncthreads();
    asm volatile("barrier.cluster.arrive.aligned;" ::: "memory");
    asm volatile("barrier.cluster.wait.aligned;" ::: "memory");

    const unsigned mbar_l  = smem_u32(&s_mbar[0]);
    const unsigned mbar_r  = mapa_u32(mbar_l, peer);
    const unsigned alpha_r = mapa_u32(smem_u32(&s_alpha[0][0]), peer) + (unsigned)cur * 8u;

    // prime peer's mbar[0] phase 0 (so the f=1 wait passes; alpha[0] needed no exchange)
    if (lane0) ARRIVE_REMOTE(mbar_r);
    int ph0 = 0, ph1 = 0;

    const float fja = (float)(lane + 2), fjb = (float)(lane + 34);
    const float da  = diag * (float)(lane + 1);
    const float db  = diag * (float)(lane + 33);

    // Rest[1] = init segment [0,1] only; frame-2 bundle
    float s0_cur, Rm, Rs;
    {
        const float* r1 = seg_base + (size_t)(1 * L_ + cur) * M_;
        s0_cur = r1[0];
        Rm = r1[1] * 2.0f + diag;
        Rs = 1.0f;
    }
    float nsa, nsb, ns0, ninit;
    {
        const float* r2 = seg_base + (size_t)(2 * L_ + cur) * M_;
        nsa = r2[lane + 1];
        nsb = r2[lane + 33];          // lane31 garbage, never used
        ns0 = r2[0];
        ninit = r2[2];
    }

    const float* pref = seg_base + (size_t)(3 * L_ + cur) * M_;

#define STEP_BODY(F, PH1, WB)                                                        \
    {                                                                                \
        /* prefetch frame F+2 bundle (long-latency, consumed at end of body) */      \
        float psa = pref[lane + 1];                                                  \
        float psb = pref[lane + 33];                                                 \
        float ps0 = pref[0];                                                         \
        float pinit = 0.0f;                                                          \
        if (PH1) { if ((F) + 2 < M_) pinit = pref[(F) + 2]; }                        \
        pref += L_ * M_;                                                             \
                                                                                     \
        /* wait for peer's alpha[F-1] pushes */                                      \
        if (WB) { WAITP(mbar_l + 8u, (unsigned)ph1); ph1 ^= 1; }                     \
        else    { WAITP(mbar_l,      (unsigned)ph0); ph0 ^= 1; }                     \
                                                                                     \
        /* beta[F-1][cur] = LSE2_prev( alpha-pair + T ) */                           \
        float2 ap = s_alpha[((F) - 1) & 1][lane];                                    \
        float Bm = redux_max_f32(ap.x);                                              \
        unsigned bu = (unsigned)(ap.y * ex2f(ap.x + treg23 - Bm));                   \
        unsigned bsum = __reduce_add_sync(0xffffffffu, bu);                          \
        float beta = (Bm - 23.0f) + lg2f((float)bsum);                               \
                                                                                     \
        /* alpha[F] pair = combine(Rest[F], beta + seg(F,F)) */                      \
        float t1 = beta + s0_cur;                                                    \
        float Am = fmaxf(Rm, t1);                                                    \
        float dd = Rm - t1;                                                          \
        float ee = ex2f(0.0f - fabsf(dd));                                           \
        float As = (dd >= 0.0f) ? (Rs + ee) : fmaf(Rs, ee, 1.0f);                    \
                                                                                     \
        if (lane0) {                                                                 \
            s_alpha[(F) & 1][cur] = make_float2(Am, As);                             \
            ST_REMOTE_V2(alpha_r + (unsigned)(((F) & 1) * (L_ * 8)), Am, As);        \
            ARRIVE_REMOTE(mbar_r + (unsigned)(((F) & 1) * 8));                       \
            s_beta[(((F) - 1) & 63) * (LH_ + 1) + w] = beta;                         \
        }                                                                            \
        __syncthreads();                                                             \
                                                                                     \
        /* Rest[F+1]: j=2..64 (+ init segment in phase 1) */                         \
        int sla = (((F) - 1 - lane) & 63) * (LH_ + 1) + w;                           \
        int slb = (((F) - 33 - lane) & 63) * (LH_ + 1) + w;                          \
        float ta = s_beta[sla] + fmaf(nsa, fja, da);                                 \
        float tb;                                                                    \
        if (PH1) tb = lane31 ? fmaf(ninit, (float)((F) + 2), diag * (float)((F) + 1))\
                             : s_beta[slb] + fmaf(nsb, fjb, db);                     \
        else     tb = lane31 ? NEGV : s_beta[slb] + fmaf(nsb, fjb, db);              \
        float m2 = redux_max_f32(fmaxf(ta, tb));                                     \
        float m24 = m2 - 24.0f;                                                      \
        unsigned ru = (unsigned)(ex2f(ta - m24) + ex2f(tb - m24));                   \
        unsigned rsum = __reduce_add_sync(0xffffffffu, ru);                          \
        float rsf = (float)rsum;                                                     \
        unsigned rb = __float_as_uint(rsf);                                          \
        int li = (int)(rb >> 23) - 127;                                              \
        Rm = m24 + (float)li;                                                        \
        Rs = __uint_as_float(rb - ((unsigned)li << 23));                             \
                                                                                     \
        s0_cur = ns0; nsa = psa; nsb = psb; ns0 = ps0; ninit = pinit;                \
    }

    for (int f = 1; f <= 61; f += 2) { STEP_BODY(f, true, 0) STEP_BODY(f + 1, true, 1) }
    for (int f = 63; f < 510; f += 2) { STEP_BODY(f, false, 0) STEP_BODY(f + 1, false, 1) }
    STEP_BODY(511, false, 0)
#undef STEP_BODY

    // ---- log_z: rank 0, warp 0 (needs peer's alpha[511] -> mbar[1], current ph1) ----
    if (rank == 0 && w == 0) {
        WAITP(mbar_l + 8u, (unsigned)ph1);
        float2 p = s_alpha[(S_ - 1) & 1][lane];
        float v = p.x + lg2f(p.y);
        float m = redux_max_f32(v);
        unsigned u = (unsigned)ex2f(v - m + 24.0f);
        unsigned s = __reduce_add_sync(0xffffffffu, u);
        if (lane == 0) out[b] = (m - 24.0f + lg2f((float)s)) * LN2_;
    }

    // keep cluster smem alive until all remote ops delivered / consumed
    asm volatile("barrier.cluster.arrive.aligned;" ::: "memory");
    asm volatile("barrier.cluster.wait.aligned;" ::: "memory");
}

extern "C" void kernel_launch(void* const* d_in, const int* in_sizes, int n_in,
                              void* d_out, int out_size) {
    const float* seg   = (const float*)d_in[0];
    const float* trans = (const float*)d_in[1];
    if (n_in >= 2 && in_sizes[0] == L_ * L_) {
        trans = (const float*)d_in[0];
        seg   = (const float*)d_in[1];
    }
    float* out = (float*)d_out;

    transpose_kernel<<<B_ * S_, 256>>>(seg);
    crf_kernel<<<B_ * 2, 512>>>(trans, out);
}

// round 9
// speedup vs baseline: 1.9121x; 1.9121x over previous
#include <cuda_runtime.h>
#include <math.h>

#define NEGV (-1e30f)

// B=8, S=512, L=32, M=64
#define B_ 8
#define S_ 512
#define L_ 32
#define M_ 64
#define SP_ (S_ + 2)          // padded frames: prefetch never needs a frame bounds check
#define LOG2E_ 1.4426950408889634f
#define LN2_   0.6931471805599453f

// scratch[b][e][cur][jm1] = segment_score[b][e-jm1][e][cur] * LOG2E  (log2 domain)
// +64 pad: lane31's unconditional psb prefetch reads one element past the last row.
__device__ float g_scratch[B_ * SP_ * L_ * M_ + 64];

__device__ __forceinline__ float ex2f(float x) {
    float y; asm("ex2.approx.ftz.f32 %0, %1;" : "=f"(y) : "f"(x)); return y;
}
__device__ __forceinline__ float lg2f(float x) {
    float y; asm("lg2.approx.ftz.f32 %0, %1;" : "=f"(y) : "f"(x)); return y;
}
__device__ __forceinline__ float redux_max_f32(float x) {
    unsigned u = __float_as_uint(x);
    unsigned k = u ^ (((unsigned)((int)u >> 31)) | 0x80000000u);      // monotone key
    unsigned r = __reduce_max_sync(0xffffffffu, k);
    return __uint_as_float(r ^ ((~((unsigned)((int)r >> 31))) | 0x80000000u));
}

// -------- pre-pass: gather band into contiguous [b][e][cur][jm1] layout, log2-scaled --------
__global__ void transpose_kernel(const float* __restrict__ seg) {
    int be = blockIdx.x;
    int b = be >> 9;
    int e = be & (S_ - 1);
    __shared__ float tile[L_][M_ + 1];
    int tid = threadIdx.x;
    for (int idx = tid; idx < M_ * L_; idx += 256) {
        int jm1 = idx >> 5;
        int c   = idx & 31;
        float v = 0.0f;
        int s = e - jm1;
        if (s >= 0) v = seg[(((size_t)b * S_ + s) * S_ + e) * L_ + c] * LOG2E_;
        tile[c][jm1] = v;
    }
    __syncthreads();
    float* out = &g_scratch[((size_t)(b * SP_ + e)) * (L_ * M_)];
    for (int idx = tid; idx < L_ * M_; idx += 256) {
        int c   = idx >> 6;
        int jm1 = idx & 63;
        out[idx] = tile[c][jm1];
    }
}

// -------- sequential recurrence: one CTA per batch, warp = cur label --------
// alpha: unnormalized (m, s) pair; beta: scalar log2, warp-private ring [cur][frame&63].
// Only s_alpha crosses warps -> single end-of-body __syncthreads; ring ordering via __syncwarp.
__global__ __launch_bounds__(1024, 1) void crf_kernel(const float* __restrict__ trans,
                                                      float* __restrict__ out) {
    __shared__ float2 s_alpha[2][L_];
    __shared__ float  s_beta[L_ * M_];     // [cur][frame & 63]

    const int b    = blockIdx.x;
    const int tid  = threadIdx.x;
    const int cur  = tid >> 5;
    const int lane = tid & 31;
    const bool lane0  = (lane == 0);
    const bool lane31 = (lane == 31);

    const float treg23 = trans[lane * L_ + cur] * LOG2E_ + 23.0f;   // T[prev=lane][cur] + bias
    const float diag   = trans[cur * L_ + cur] * LOG2E_;
    const float* seg_base = &g_scratch[((size_t)(b * SP_)) * (L_ * M_)];
    float* ring = &s_beta[cur * M_];

    for (int i = tid; i < L_ * M_; i += 1024) s_beta[i] = NEGV;
    if (tid < L_) s_alpha[0][tid] = make_float2(seg_base[tid * M_], 1.0f);

    const float fja = (float)(lane + 2), fjb = (float)(lane + 34);
    const float da  = diag * (float)(lane + 1);
    const float db  = diag * (float)(lane + 33);

    // Rest[1] = init segment [0,1] only; frame-2 bundle
    float s0_cur, Rm, Rs;
    {
        const float* r1 = seg_base + (size_t)(1 * L_ + cur) * M_;
        s0_cur = r1[0];
        Rm = r1[1] * 2.0f + diag;
        Rs = 1.0f;
    }
    float nsa, nsb, ns0, ninit;
    {
        const float* r2 = seg_base + (size_t)(2 * L_ + cur) * M_;
        nsa = r2[lane + 1];
        nsb = r2[lane + 33];          // lane31 slot unused
        ns0 = r2[0];
        ninit = r2[2];
    }
    __syncthreads();

    const float* pref = seg_base + (size_t)(3 * L_ + cur) * M_;   // row for frame F+2 at F=1

#define STEP_BODY(F, PH1)                                                            \
    {                                                                                \
        /* prefetch frame F+2 bundle (long-latency, consumed at end of body) */      \
        float psa = pref[lane + 1];                                                  \
        float psb = pref[lane + 33];                                                 \
        float ps0 = pref[0];                                                         \
        float pinit = 0.0f;                                                          \
        if (PH1) { if ((F) + 2 < M_) pinit = pref[(F) + 2]; }                        \
        pref += L_ * M_;                                                             \
                                                                                     \
        /* beta[F-1][cur] = LSE2_prev( alpha-pair + T ) */                           \
        float2 ap = s_alpha[((F) - 1) & 1][lane];                                    \
        float Bm = redux_max_f32(ap.x);                                              \
        unsigned bu = (unsigned)(ap.y * ex2f(ap.x + treg23 - Bm));                   \
        unsigned bsum = __reduce_add_sync(0xffffffffu, bu);                          \
        float beta = (Bm - 23.0f) + lg2f((float)bsum);                               \
                                                                                     \
        /* alpha[F] pair = combine(Rest[F], beta + seg(F,F)) */                      \
        float t1 = beta + s0_cur;                                                    \
        float Am = fmaxf(Rm, t1);                                                    \
        float dd = Rm - t1;                                                          \
        float ee = ex2f(0.0f - fabsf(dd));                                           \
        float As = (dd >= 0.0f) ? (Rs + ee) : fmaf(Rs, ee, 1.0f);                    \
                                                                                     \
        if (lane0) {                                                                 \
            s_alpha[(F) & 1][cur] = make_float2(Am, As);                             \
            ring[((F) - 1) & 63] = beta;                                             \
        }                                                                            \
        __syncwarp();                                                                \
                                                                                     \
        /* Rest[F+1]: j=2..64 (+ init segment in phase 1); ring is warp-private */   \
        int ia = ((F) - 1 - lane) & 63;                                              \
        float ta = ring[ia] + fmaf(nsa, fja, da);                                    \
        float tbeta = ring[ia ^ 32];                                                 \
        float tb;                                                                    \
        if (PH1) tb = lane31 ? fmaf(ninit, (float)((F) + 2), diag * (float)((F) + 1))\
                             : tbeta + fmaf(nsb, fjb, db);                           \
        else     tb = lane31 ? NEGV : tbeta + fmaf(nsb, fjb, db);                    \
        float m2 = redux_max_f32(fmaxf(ta, tb));                                     \
        float m24 = m2 - 24.0f;                                                      \
        unsigned ru = (unsigned)(ex2f(ta - m24) + ex2f(tb - m24));                   \
        unsigned rsum = __reduce_add_sync(0xffffffffu, ru);                          \
        float rsf = (float)rsum;                                                     \
        unsigned rb = __float_as_uint(rsf);                                          \
        int li = (int)(rb >> 23) - 127;                                              \
        Rm = m24 + (float)li;                                                        \
        Rs = __uint_as_float(rb - ((unsigned)li << 23));                             \
                                                                                     \
        s0_cur = ns0; nsa = psa; nsb = psb; ns0 = ps0; ninit = pinit;                \
        __syncthreads();   /* protects s_alpha: next beta read + WAR on buffers */   \
    }

    for (int f = 1; f <= 61; f += 2) { STEP_BODY(f, true) STEP_BODY(f + 1, true) }
    for (int f = 63; f < 510; f += 2) { STEP_BODY(f, false) STEP_BODY(f + 1, false) }
    STEP_BODY(511, false)
#undef STEP_BODY

    // ---- log_z = LN2 * LSE2_cur ( alpha[S-1] pair ) ----
    if (cur == 0) {
        float2 p = s_alpha[(S_ - 1) & 1][lane];
        float v = p.x + lg2f(p.y);
        float m = redux_max_f32(v);
        unsigned u = (unsigned)ex2f(v - m + 24.0f);
        unsigned s = __reduce_add_sync(0xffffffffu, u);
        if (lane == 0) out[b] = (m - 24.0f + lg2f((float)s)) * LN2_;
    }
}

extern "C" void kernel_launch(void* const* d_in, const int* in_sizes, int n_in,
                              void* d_out, int out_size) {
    const float* seg   = (const float*)d_in[0];
    const float* trans = (const float*)d_in[1];
    if (n_in >= 2 && in_sizes[0] == L_ * L_) {
        trans = (const float*)d_in[0];
        seg   = (const float*)d_in[1];
    }
    float* out = (float*)d_out;

    transpose_kernel<<<B_ * S_, 256>>>(seg);
    crf_kernel<<<B_, 1024>>>(trans, out);
}